// round 5
// baseline (speedup 1.0000x reference)
#include <cuda_runtime.h>

// h: [N_ROWS, DIM] fp32; S: [DIM, DIM] fp32 diagonal ±1.
// out = h @ S.T = h * diag(S) broadcast over rows — pure streaming op.
//
// R5: 256-bit global loads/stores (Blackwell LDG.E.256 / STG.256) to halve
// LSU wavefront count (L1 was ~66% busy and co-limiting). Default stores
// (stcs regressed in R4). Front-batched loads, col-invariant signs.

__device__ __forceinline__ void ldg256(const float* __restrict__ p, float r[8]) {
    asm volatile("ld.global.nc.v8.f32 {%0,%1,%2,%3,%4,%5,%6,%7}, [%8];"
                 : "=f"(r[0]), "=f"(r[1]), "=f"(r[2]), "=f"(r[3]),
                   "=f"(r[4]), "=f"(r[5]), "=f"(r[6]), "=f"(r[7])
                 : "l"(p));
}

__device__ __forceinline__ void stg256(float* __restrict__ p, const float r[8]) {
    asm volatile("st.global.v8.f32 [%0], {%1,%2,%3,%4,%5,%6,%7,%8};"
                 :: "l"(p),
                    "f"(r[0]), "f"(r[1]), "f"(r[2]), "f"(r[3]),
                    "f"(r[4]), "f"(r[5]), "f"(r[6]), "f"(r[7])
                 : "memory");
}

// Exact-shape kernel: n_vec8 == ITERS * totalThreads, totalThreads % dim8 == 0.
template <int ITERS>
__global__ __launch_bounds__(256)
void parity_scale_v8(const float* __restrict__ h,
                     const float* __restrict__ S,
                     float* __restrict__ out,
                     int dim8, int dim) {
    const long long stride8 = (long long)gridDim.x * blockDim.x;  // float8 units
    const long long i0 = (long long)blockIdx.x * blockDim.x + threadIdx.x;

    // Column invariant: stride8 % dim8 == 0 guaranteed by host.
    int col8 = (int)(i0 % (long long)dim8);
    int c = col8 * 8;

    float s[8];
    #pragma unroll
    for (int j = 0; j < 8; j++) {
        s[j] = S[(long long)(c + j) * dim + (c + j)];
    }

    float v[ITERS][8];
    #pragma unroll
    for (int i = 0; i < ITERS; i++) {
        ldg256(h + (i0 + (long long)i * stride8) * 8, v[i]);
    }
    #pragma unroll
    for (int i = 0; i < ITERS; i++) {
        #pragma unroll
        for (int j = 0; j < 8; j++) v[i][j] *= s[j];
        stg256(out + (i0 + (long long)i * stride8) * 8, v[i]);
    }
}

// ---------------- Generic fallback (float4, default stores) -----------------
__global__ void parity_scale_generic(const float4* __restrict__ h,
                                     const float* __restrict__ S,
                                     float4* __restrict__ out,
                                     long long n_vec4, int dim4, int dim) {
    long long idx0 = (long long)blockIdx.x * blockDim.x + threadIdx.x;
    long long stride = (long long)gridDim.x * blockDim.x;  // multiple of dim4

    int col4 = (int)(idx0 % (long long)dim4);
    int c = col4 * 4;

    float4 s;
    s.x = S[(long long)(c + 0) * dim + (c + 0)];
    s.y = S[(long long)(c + 1) * dim + (c + 1)];
    s.z = S[(long long)(c + 2) * dim + (c + 2)];
    s.w = S[(long long)(c + 3) * dim + (c + 3)];

    #pragma unroll 4
    for (long long idx = idx0; idx < n_vec4; idx += stride) {
        float4 v = __ldcg(&h[idx]);
        v.x *= s.x; v.y *= s.y; v.z *= s.z; v.w *= s.w;
        out[idx] = v;
    }
}

static long long gcd_ll(long long a, long long b) {
    while (b) { long long t = a % b; a = b; b = t; }
    return a;
}

extern "C" void kernel_launch(void* const* d_in, const int* in_sizes, int n_in,
                              void* d_out, int out_size) {
    const float* h = (const float*)d_in[0];
    const float* S = (const float*)d_in[1];
    float* out = (float*)d_out;

    // in_sizes[1] = DIM*DIM -> integer sqrt
    int dim = 1;
    {
        long long s = in_sizes[1];
        long long lo = 1, hi = 65536;
        while (lo < hi) {
            long long mid = (lo + hi + 1) / 2;
            if (mid * mid <= s) lo = mid; else hi = mid - 1;
        }
        dim = (int)lo;
    }

    long long total = in_sizes[0];        // N_ROWS * DIM
    const int threads = 256;

    // 256-bit path: dim divisible by 8, exact tiling with ITERS=4.
    if (dim % 8 == 0 && total % 8 == 0) {
        long long n_vec8 = total / 8;
        int dim8 = dim / 8;
        const int ITERS = 4;
        long long T = n_vec8 / ITERS;
        bool exact = (n_vec8 % ITERS == 0) &&
                     (T % threads == 0) &&
                     (T % dim8 == 0) &&
                     (T / threads <= 2147483647LL);
        if (exact) {
            int blocks = (int)(T / threads);
            parity_scale_v8<ITERS><<<blocks, threads>>>(h, S, out, dim8, dim);
            return;
        }
    }

    // Generic fallback: grid-stride multiple of dim4 (col invariance).
    long long n_vec4 = total / 4;
    int dim4 = dim / 4;
    long long m = (long long)dim4 / gcd_ll(threads, dim4);
    long long want = 148LL * 32;
    long long blocks = ((want + m - 1) / m) * m;
    long long cover = (n_vec4 + threads - 1) / threads;
    long long cover_r = ((cover + m - 1) / m) * m;
    if (blocks > cover_r) blocks = cover_r;
    if (blocks < m) blocks = m;

    parity_scale_generic<<<(int)blocks, threads>>>(
        (const float4*)h, S, (float4*)out, n_vec4, dim4, dim);
}